// round 7
// baseline (speedup 1.0000x reference)
#include <cuda_runtime.h>
#include <cuda_bf16.h>
#include <math.h>

// Problem constants
#define H_NF 128
#define N_GAUSS 50
#define MAX_NODES 100000

#define EPB 512   // edges per block
#define TPB 256   // threads per block
#define EPW 64    // edges per warp

// step = 10/49 ; exp(coeff*(d-o)^2) = 2^( -(A*d - A*o)^2 ), A = sqrt(0.5*log2e)/step
#define STEP_D    (10.0 / 49.0)
#define A_CONST   ((float)(0.8493255219056067 / STEP_D))
#define AS_CONST  ((float)0.8493255219056067)

// Padded coords scratch: [N] float4. Static device array (no alloc).
__device__ float4 g_coords4[MAX_NODES];

// ---------------------------------------------------------------------------
// Prologue: pad coords [N,3] -> float4 [N]
// ---------------------------------------------------------------------------
__global__ void pad_coords_kernel(const float* __restrict__ coords, int n_nodes) {
    int i = blockIdx.x * blockDim.x + threadIdx.x;
    if (i < n_nodes) {
        float4 v;
        v.x = __ldg(&coords[(size_t)i * 3 + 0]);
        v.y = __ldg(&coords[(size_t)i * 3 + 1]);
        v.z = __ldg(&coords[(size_t)i * 3 + 2]);
        v.w = 0.0f;
        g_coords4[i] = v;
    }
}

// ---------------------------------------------------------------------------
// Fused: node-embedding blocks + edge blocks (register-resident distances)
// ---------------------------------------------------------------------------
__global__ __launch_bounds__(TPB) void fused_kernel(
    const int*   __restrict__ atomic_ns,   // [N]
    const int*   __restrict__ edge_index,  // [2, E]
    const float4* __restrict__ weight4,    // [100, 32] as float4
    float4* __restrict__ out_node4,        // [N, 32] as float4
    float*  __restrict__ out_eembs,        // [E, 50]
    float*  __restrict__ out_ew,           // [E]
    long long n_edges,
    int n_nodes,
    int edge_blocks)
{
    const int tid = threadIdx.x;

    // ---------------- node-embedding blocks ----------------
    if (blockIdx.x >= edge_blocks) {
        int nb   = blockIdx.x - edge_blocks;
        int node = nb * (TPB / 32) + (tid >> 5);
        int lane = tid & 31;
        if (node < n_nodes) {
            int a = __ldg(&atomic_ns[node]);
            float4 v = __ldg(&weight4[(size_t)a * 32 + lane]);
            __stcs(&out_node4[(size_t)node * 32 + lane], v);
        }
        return;
    }

    // ---------------- edge blocks ----------------
    const long long e0 = (long long)blockIdx.x * EPB;
    const bool full = (e0 + EPB) <= n_edges;

    if (full) {
        // Warp-local, smem-free pipeline. Warp w owns 64 edges; lane owns
        // edges (2*lane, 2*lane+1) of that segment.
        const int w    = tid >> 5;
        const int lane = tid & 31;
        const long long we0 = e0 + (long long)w * EPW;

        // Phase 1: coalesced int2 index loads, 4 batched float4 gathers.
        const int2* __restrict__ ei2 = (const int2*)edge_index;
        int2 iv = __ldcg(&ei2[(size_t)((we0 >> 1) + lane)]);
        int2 jv = __ldcg(&ei2[(size_t)(((n_edges + we0) >> 1) + lane)]);
        float4 a0 = __ldcg(&g_coords4[iv.x]);
        float4 b0 = __ldcg(&g_coords4[jv.x]);
        float4 a1 = __ldcg(&g_coords4[iv.y]);
        float4 b1 = __ldcg(&g_coords4[jv.y]);
        float dx0 = a0.x - b0.x, dy0 = a0.y - b0.y, dz0 = a0.z - b0.z;
        float dx1 = a1.x - b1.x, dy1 = a1.y - b1.y, dz1 = a1.z - b1.z;
        float dist0 = sqrtf(fmaf(dx0, dx0, fmaf(dy0, dy0, dz0 * dz0)));
        float dist1 = sqrtf(fmaf(dx1, dx1, fmaf(dy1, dy1, dz1 * dz1)));
        float2 dw; dw.x = dist0; dw.y = dist1;
        __stcs(&((float2*)out_ew)[(we0 >> 1) + lane], dw);
        float r0 = dist0 * A_CONST;   // scaled dist, edge 2*lane
        float r1 = dist1 * A_CONST;   // scaled dist, edge 2*lane+1

        // Phase 2: 64 edges * 50 floats = 800 float4, 25 per lane.
        // Distances fetched via shuffle (no smem).
        float4* __restrict__ base4 =
            reinterpret_cast<float4*>(out_eembs + we0 * N_GAUSS);
        int f  = 4 * lane;
        int le = f / 50;
        int g  = f - 50 * le;
        #pragma unroll
        for (int it = 0; it < 25; ++it) {
            int  half = le >> 1;
            bool odd  = (le & 1);
            float sA = __shfl_sync(0xffffffffu, r0, half);
            float sB = __shfl_sync(0xffffffffu, r1, half);
            float sC = __shfl_sync(0xffffffffu, r0, half + 1); // wraps at 32; only used valid
            float u  = odd ? sB : sA;
            float un = odd ? sC : sB;
            bool span = (g == 48);
            float og = (float)g * AS_CONST;
            float d0 = u - og;
            float d1 = d0 - AS_CONST;
            float d2 = span ? un : (d1 - AS_CONST);
            float d3 = d2 - AS_CONST;
            float4 r;
            r.x = exp2f(d0 * -d0);
            r.y = exp2f(d1 * -d1);
            r.z = exp2f(d2 * -d2);
            r.w = exp2f(d3 * -d3);
            __stcs(&base4[lane + it * 32], r);
            // advance flat float index by 128: +2 edges, +28 gauss
            g += 28; le += 2;
            if (g >= 50) { g -= 50; le += 1; }
        }
    } else {
        // Guarded tail block (rare): block-wide smem path.
        __shared__ float s_dist[EPB + 8];
        if (tid < 8) s_dist[EPB + tid] = 0.0f;
        #pragma unroll
        for (int s = 0; s < EPB / TPB; ++s) {
            long long e = e0 + tid + s * TPB;
            if (e < n_edges) {
                int i = __ldcg(&edge_index[e]);
                int j = __ldcg(&edge_index[n_edges + e]);
                float4 a = __ldcg(&g_coords4[i]);
                float4 b = __ldcg(&g_coords4[j]);
                float dx = a.x - b.x, dy = a.y - b.y, dz = a.z - b.z;
                float dist = sqrtf(fmaf(dx, dx, fmaf(dy, dy, dz * dz)));
                __stcs(&out_ew[e], dist);
                s_dist[tid + s * TPB] = dist * A_CONST;
            } else {
                s_dist[tid + s * TPB] = 0.0f;
            }
        }
        __syncthreads();
        int rem = (int)(n_edges - e0);
        int total = rem * (N_GAUSS / 2);
        float2* __restrict__ base2 =
            reinterpret_cast<float2*>(out_eembs + e0 * N_GAUSS);
        for (int k = tid; k < total; k += TPB) {
            int le = k / 25;
            int p  = k - le * 25;
            float u  = s_dist[le];
            float o0 = (float)(2 * p) * AS_CONST;
            float d0 = u - o0;
            float d1 = d0 - AS_CONST;
            float2 r;
            r.x = exp2f(d0 * -d0);
            r.y = exp2f(d1 * -d1);
            __stcs(&base2[k], r);
        }
    }
}

// ---------------------------------------------------------------------------
// Inputs (metadata order):
//   0: atomic_ns int32 [N], 1: edge_index int32 [2,E], 2: coords f32 [N,3],
//   3: batch_node_vec int32 [N] (unused), 4: node_emb_weight f32 [100,128]
// Output (f32): node_embs [N,128] | edge_embs [E,50] | edge_weights [E]
// ---------------------------------------------------------------------------
extern "C" void kernel_launch(void* const* d_in, const int* in_sizes, int n_in,
                              void* d_out, int out_size) {
    const int*   atomic_ns  = (const int*)d_in[0];
    const int*   edge_index = (const int*)d_in[1];
    const float* coords     = (const float*)d_in[2];
    const float* weight     = (const float*)d_in[4];

    const int       n_nodes = in_sizes[0];
    const long long n_edges = (long long)in_sizes[1] / 2;

    float* out = (float*)d_out;
    float* out_node  = out;
    float* out_eembs = out + (size_t)n_nodes * H_NF;
    float* out_ew    = out_eembs + (size_t)n_edges * N_GAUSS;

    // Prologue: pad coords into float4 scratch
    {
        int tpb = 256;
        int blocks = (n_nodes + tpb - 1) / tpb;
        pad_coords_kernel<<<blocks, tpb>>>(coords, n_nodes);
    }

    int edge_blocks = (int)((n_edges + EPB - 1) / EPB);
    int node_blocks = (n_nodes + (TPB / 32) - 1) / (TPB / 32);

    fused_kernel<<<edge_blocks + node_blocks, TPB>>>(
        atomic_ns, edge_index,
        (const float4*)weight,
        (float4*)out_node, out_eembs, out_ew,
        n_edges, n_nodes, edge_blocks);
}

// round 8
// speedup vs baseline: 1.0003x; 1.0003x over previous
#include <cuda_runtime.h>
#include <cuda_bf16.h>
#include <math.h>

// Problem constants
#define H_NF 128
#define N_GAUSS 50
#define MAX_NODES 100000

#define EPB 512   // edges per block
#define TPB 256   // threads per block
#define EPW 64    // edges per warp

// step = 10/49 ; exp(coeff*(d-o)^2) = 2^( -(A*d - A*o)^2 ), A = sqrt(0.5*log2e)/step
#define STEP_D    (10.0 / 49.0)
#define A_CONST   ((float)(0.8493255219056067 / STEP_D))
#define AS_CONST  ((float)0.8493255219056067)

// Padded coords scratch: [N] float4. Static device array (no alloc).
__device__ float4 g_coords4[MAX_NODES];

// ---------------------------------------------------------------------------
// Prologue: pad coords [N,3] -> float4 [N]
// ---------------------------------------------------------------------------
__global__ void pad_coords_kernel(const float* __restrict__ coords, int n_nodes) {
    int i = blockIdx.x * blockDim.x + threadIdx.x;
    if (i < n_nodes) {
        float4 v;
        v.x = __ldg(&coords[(size_t)i * 3 + 0]);
        v.y = __ldg(&coords[(size_t)i * 3 + 1]);
        v.z = __ldg(&coords[(size_t)i * 3 + 2]);
        v.w = 0.0f;
        g_coords4[i] = v;
    }
}

// ---------------------------------------------------------------------------
// Fused: every block does its share of node embeddings + one edge tile.
// ---------------------------------------------------------------------------
__global__ __launch_bounds__(TPB) void fused_kernel(
    const int*   __restrict__ atomic_ns,   // [N]
    const int*   __restrict__ edge_index,  // [2, E]
    const float4* __restrict__ weight4,    // [100, 32] as float4
    float4* __restrict__ out_node4,        // [N, 32] as float4
    float*  __restrict__ out_eembs,        // [E, 50]
    float*  __restrict__ out_ew,           // [E]
    long long n_edges,
    int n_nodes,
    int npb)                                // nodes per block
{
    const int tid  = threadIdx.x;
    const int w    = tid >> 5;
    const int lane = tid & 31;

    // ---------------- node-embedding duty (interleaved with edge work) -----
    {
        int nb0 = blockIdx.x * npb;
        for (int s = 2 * w; s < npb; s += 2 * (TPB / 32)) {
            int nA = nb0 + s;
            int nB = nA + 1;
            bool vA = (nA < n_nodes);
            bool vB = (nB < n_nodes);
            int aA = vA ? __ldg(&atomic_ns[nA]) : 0;
            int aB = vB ? __ldg(&atomic_ns[nB]) : 0;
            float4 wA, wB;
            if (vA) wA = __ldg(&weight4[(size_t)aA * 32 + lane]);
            if (vB) wB = __ldg(&weight4[(size_t)aB * 32 + lane]);
            if (vA) __stcs(&out_node4[(size_t)nA * 32 + lane], wA);
            if (vB) __stcs(&out_node4[(size_t)nB * 32 + lane], wB);
        }
    }

    // ---------------- edge tile ----------------
    const long long e0 = (long long)blockIdx.x * EPB;
    if (e0 >= n_edges) return;
    const bool full = (e0 + EPB) <= n_edges;

    if (full) {
        // Warp-local, smem-free pipeline. Warp w owns 64 edges; lane owns
        // edges (2*lane, 2*lane+1) of that segment.
        const long long we0 = e0 + (long long)w * EPW;

        // Phase 1: coalesced int2 index loads, 4 batched float4 gathers.
        const int2* __restrict__ ei2 = (const int2*)edge_index;
        int2 iv = __ldcg(&ei2[(size_t)((we0 >> 1) + lane)]);
        int2 jv = __ldcg(&ei2[(size_t)(((n_edges + we0) >> 1) + lane)]);
        float4 a0 = __ldcg(&g_coords4[iv.x]);
        float4 b0 = __ldcg(&g_coords4[jv.x]);
        float4 a1 = __ldcg(&g_coords4[iv.y]);
        float4 b1 = __ldcg(&g_coords4[jv.y]);
        float dx0 = a0.x - b0.x, dy0 = a0.y - b0.y, dz0 = a0.z - b0.z;
        float dx1 = a1.x - b1.x, dy1 = a1.y - b1.y, dz1 = a1.z - b1.z;
        float dist0 = sqrtf(fmaf(dx0, dx0, fmaf(dy0, dy0, dz0 * dz0)));
        float dist1 = sqrtf(fmaf(dx1, dx1, fmaf(dy1, dy1, dz1 * dz1)));
        float2 dw; dw.x = dist0; dw.y = dist1;
        __stcs(&((float2*)out_ew)[(we0 >> 1) + lane], dw);
        float r0 = dist0 * A_CONST;   // scaled dist, edge 2*lane
        float r1 = dist1 * A_CONST;   // scaled dist, edge 2*lane+1

        // Phase 2: 64 edges * 50 floats = 800 float4, 25 per lane.
        // Distances fetched via shuffle (no smem).
        float4* __restrict__ base4 =
            reinterpret_cast<float4*>(out_eembs + we0 * N_GAUSS);
        int f  = 4 * lane;
        int le = f / 50;
        int g  = f - 50 * le;
        #pragma unroll
        for (int it = 0; it < 25; ++it) {
            int  half = le >> 1;
            bool odd  = (le & 1);
            float sA = __shfl_sync(0xffffffffu, r0, half);
            float sB = __shfl_sync(0xffffffffu, r1, half);
            float sC = __shfl_sync(0xffffffffu, r0, half + 1); // span case only
            float u  = odd ? sB : sA;
            float un = odd ? sC : sB;
            bool span = (g == 48);
            float og = (float)g * AS_CONST;
            float d0 = u - og;
            float d1 = d0 - AS_CONST;
            float d2 = span ? un : (d1 - AS_CONST);
            float d3 = d2 - AS_CONST;
            float4 r;
            r.x = exp2f(d0 * -d0);
            r.y = exp2f(d1 * -d1);
            r.z = exp2f(d2 * -d2);
            r.w = exp2f(d3 * -d3);
            __stcs(&base4[lane + it * 32], r);
            // advance flat float index by 128: +2 edges, +28 gauss
            g += 28; le += 2;
            if (g >= 50) { g -= 50; le += 1; }
        }
    } else {
        // Guarded tail block (rare): block-wide smem path.
        __shared__ float s_dist[EPB + 8];
        if (tid < 8) s_dist[EPB + tid] = 0.0f;
        #pragma unroll
        for (int s = 0; s < EPB / TPB; ++s) {
            long long e = e0 + tid + s * TPB;
            if (e < n_edges) {
                int i = __ldcg(&edge_index[e]);
                int j = __ldcg(&edge_index[n_edges + e]);
                float4 a = __ldcg(&g_coords4[i]);
                float4 b = __ldcg(&g_coords4[j]);
                float dx = a.x - b.x, dy = a.y - b.y, dz = a.z - b.z;
                float dist = sqrtf(fmaf(dx, dx, fmaf(dy, dy, dz * dz)));
                __stcs(&out_ew[e], dist);
                s_dist[tid + s * TPB] = dist * A_CONST;
            } else {
                s_dist[tid + s * TPB] = 0.0f;
            }
        }
        __syncthreads();
        int rem = (int)(n_edges - e0);
        int total = rem * (N_GAUSS / 2);
        float2* __restrict__ base2 =
            reinterpret_cast<float2*>(out_eembs + e0 * N_GAUSS);
        for (int k = tid; k < total; k += TPB) {
            int le = k / 25;
            int p  = k - le * 25;
            float u  = s_dist[le];
            float o0 = (float)(2 * p) * AS_CONST;
            float d0 = u - o0;
            float d1 = d0 - AS_CONST;
            float2 r;
            r.x = exp2f(d0 * -d0);
            r.y = exp2f(d1 * -d1);
            __stcs(&base2[k], r);
        }
    }
}

// ---------------------------------------------------------------------------
// Inputs (metadata order):
//   0: atomic_ns int32 [N], 1: edge_index int32 [2,E], 2: coords f32 [N,3],
//   3: batch_node_vec int32 [N] (unused), 4: node_emb_weight f32 [100,128]
// Output (f32): node_embs [N,128] | edge_embs [E,50] | edge_weights [E]
// ---------------------------------------------------------------------------
extern "C" void kernel_launch(void* const* d_in, const int* in_sizes, int n_in,
                              void* d_out, int out_size) {
    const int*   atomic_ns  = (const int*)d_in[0];
    const int*   edge_index = (const int*)d_in[1];
    const float* coords     = (const float*)d_in[2];
    const float* weight     = (const float*)d_in[4];

    const int       n_nodes = in_sizes[0];
    const long long n_edges = (long long)in_sizes[1] / 2;

    float* out = (float*)d_out;
    float* out_node  = out;
    float* out_eembs = out + (size_t)n_nodes * H_NF;
    float* out_ew    = out_eembs + (size_t)n_edges * N_GAUSS;

    // Prologue: pad coords into float4 scratch
    {
        int tpb = 256;
        int blocks = (n_nodes + tpb - 1) / tpb;
        pad_coords_kernel<<<blocks, tpb>>>(coords, n_nodes);
    }

    int edge_blocks = (int)((n_edges + EPB - 1) / EPB);
    // nodes per block (even, so the 2-per-warp loop covers all)
    int npb = (n_nodes + edge_blocks - 1) / edge_blocks;
    npb = (npb + 1) & ~1;
    // ensure grid covers all nodes even if edge_blocks is tiny
    int blocks = edge_blocks;
    if ((long long)blocks * npb < n_nodes)
        blocks = (n_nodes + npb - 1) / npb;

    fused_kernel<<<blocks, TPB>>>(
        atomic_ns, edge_index,
        (const float4*)weight,
        (float4*)out_node, out_eembs, out_ew,
        n_edges, n_nodes, npb);
}